// round 17
// baseline (speedup 1.0000x reference)
#include <cuda_runtime.h>
#include <cuda_bf16.h>
#include <cstdint>

#define NTIME 2000
#define NBATCH 128
#define INSIZE 256
#define OSIZE 40
#define NTRANS 32
#define NROWS (NTIME * NBATCH)
#define CHUNK 10
#define NCHUNK (NTIME / CHUNK)   // 200
#define GRP 20
#define NGRP (NCHUNK / GRP)      // 10

// Prepacked W as bf16 hi/lo pairs, linear layout matching k1's B smem:
// u32 index n*132 + q  (q = k/2, 128 real + 4 pad per row).
__device__ uint32_t g_wbh[OSIZE * 132];
__device__ uint32_t g_wbl[OSIZE * 132];
// exp(trans), TRANSPOSED layout: (t, b, ch) at [(t*32+ch)*128 + b].
__device__ float g_ew[(NTIME + 8) * NBATCH * NTRANS];
// Normalized per-chunk 8x8 matrices, coalesced: float4 idx (c*16+q)*128 + b.
__device__ float g_chunkM[NCHUNK * NBATCH * 64];
__device__ int   g_chunkE[NCHUNK * NBATCH];     // power-of-2 exponents
// Group matrices (products of 20 chunks), +1 group pad.
__device__ float g_grpM[(NGRP + 1) * NBATCH * 64];
__device__ int   g_grpE[NGRP * NBATCH];
__device__ float g_logZ[NBATCH];   // already divided by NTIME

// ---------------- f32x2 packed helpers (Blackwell) ----------------
__device__ __forceinline__ unsigned long long pack2(float lo, float hi) {
    unsigned long long r;
    asm("mov.b64 %0, {%1, %2};" : "=l"(r) : "f"(lo), "f"(hi));
    return r;
}
__device__ __forceinline__ void unpack2(unsigned long long v, float& lo, float& hi) {
    asm("mov.b64 {%0, %1}, %2;" : "=f"(lo), "=f"(hi) : "l"(v));
}
__device__ __forceinline__ unsigned long long fma2(unsigned long long a,
                                                   unsigned long long b,
                                                   unsigned long long c) {
    unsigned long long d;
    asm("fma.rn.f32x2 %0, %1, %2, %3;" : "=l"(d) : "l"(a), "l"(b), "l"(c));
    return d;
}
__device__ __forceinline__ unsigned long long add2(unsigned long long a,
                                                   unsigned long long b) {
    unsigned long long d;
    asm("add.rn.f32x2 %0, %1, %2;" : "=l"(d) : "l"(a), "l"(b));
    return d;
}
__device__ __forceinline__ unsigned long long mul2(unsigned long long a,
                                                   unsigned long long b) {
    unsigned long long d;
    asm("mul.rn.f32x2 %0, %1, %2;" : "=l"(d) : "l"(a), "l"(b));
    return d;
}

__device__ __forceinline__ float softplus_f(float v) {
    // matches jax.nn.softplus = max(v,0) + log1p(exp(-|v|))
    return fmaxf(v, 0.0f) + log1pf(expf(-fabsf(v)));
}

__device__ __forceinline__ uint32_t smem_u32(const void* p) {
    uint32_t a;
    asm("{ .reg .u64 t; cvta.to.shared.u64 t, %1; cvt.u32.u64 %0, t; }"
        : "=r"(a) : "l"(p));
    return a;
}

// ---------------- mma.sync helpers (portable sm_80+ path) ----------------
__device__ __forceinline__ void ldm_x4(uint32_t& r0, uint32_t& r1,
                                       uint32_t& r2, uint32_t& r3, uint32_t addr) {
    asm volatile("ldmatrix.sync.aligned.m8n8.x4.shared.b16 {%0,%1,%2,%3}, [%4];"
                 : "=r"(r0), "=r"(r1), "=r"(r2), "=r"(r3) : "r"(addr));
}
__device__ __forceinline__ void ldm_x2(uint32_t& r0, uint32_t& r1, uint32_t addr) {
    asm volatile("ldmatrix.sync.aligned.m8n8.x2.shared.b16 {%0,%1}, [%2];"
                 : "=r"(r0), "=r"(r1) : "r"(addr));
}
__device__ __forceinline__ void mma_bf16(float* d, const uint32_t* a,
                                         const uint32_t* b) {
    asm volatile(
        "mma.sync.aligned.m16n8k16.row.col.f32.bf16.bf16.f32 "
        "{%0,%1,%2,%3}, {%4,%5,%6,%7}, {%8,%9}, {%0,%1,%2,%3};"
        : "+f"(d[0]), "+f"(d[1]), "+f"(d[2]), "+f"(d[3])
        : "r"(a[0]), "r"(a[1]), "r"(a[2]), "r"(a[3]), "r"(b[0]), "r"(b[1]));
}

// ---------------- Kernel 0: prepack W -> bf16 hi/lo (once) ------------------
__global__ void __launch_bounds__(256) k0_prepw(const float* __restrict__ W)
{
    int idx = blockIdx.x * 256 + threadIdx.x;
    if (idx >= OSIZE * 132) return;
    int n = idx / 132, q = idx - n * 132;
    uint32_t hp = 0, lp = 0;
    if (q < 128) {
        float2 wv = ((const float2*)W)[(size_t)n * 128 + q];
        float h0 = (float)__float2bfloat16(wv.x);
        float h1 = (float)__float2bfloat16(wv.y);
        asm("cvt.rn.bf16x2.f32 %0, %1, %2;" : "=r"(hp) : "f"(h1), "f"(h0));
        asm("cvt.rn.bf16x2.f32 %0, %1, %2;" : "=r"(lp) : "f"(wv.y - h1), "f"(wv.x - h0));
    }
    g_wbh[idx] = hp;
    g_wbl[idx] = lp;
}

// ---------------- Kernel 1: split-bf16 mma.sync GEMM + activations ----------
// One CTA = one timestep t (128 rows), 4 warps; warp w owns rows [w*32,w*32+32)
// (2 m16 tiles) x 40 cols (5 n8 tiles). y = Ah*Bh + Ah*Bl + Al*Bh.
// A staged in 32-k chunks (80B stride -> conflict-free ldmatrix, 20KB total)
// so smem = 64.5KB -> 3 CTAs/SM = 12 warps/SM. B copied prepacked (no cvt).
#define A_STRIDE_B 80                // bytes per A row (32 bf16 + pad)
#define B_STRIDE_B 528               // bytes per B row (264 bf16)
#define SM_BIAS 0
#define SM_BH   1024
#define SM_BL   (SM_BH + OSIZE * B_STRIDE_B)    // 1024+21120 = 22144
#define SM_AH   (SM_BL + OSIZE * B_STRIDE_B)    // 43264 (mod 128 == 0)
#define SM_AL   (SM_AH + 128 * A_STRIDE_B)      // 53504
#define K1_SMEM 64512                // AH..AL end 63744; ystage needs 20992 from AH

__global__ void __launch_bounds__(128, 3)
k1_gemm_mma(const float* __restrict__ x, const float* __restrict__ W,
            const float* __restrict__ bias, float* __restrict__ out)
{
    extern __shared__ __align__(1024) unsigned char smem[];
    uint32_t smb = smem_u32(smem);
    int tid = threadIdx.x;
    int w = tid >> 5;
    int lane = tid & 31;

    if (tid < OSIZE) ((float*)(smem + SM_BIAS))[tid] = bias[tid];

    // ---- stage B: straight coalesced copy of prepacked hi/lo ----
    for (int idx = tid; idx < OSIZE * 132; idx += 128) {
        ((uint32_t*)(smem + SM_BH))[idx] = g_wbh[idx];
        ((uint32_t*)(smem + SM_BL))[idx] = g_wbl[idx];
    }

    float acc[2][5][4];
#pragma unroll
    for (int mt = 0; mt < 2; mt++)
#pragma unroll
        for (int nt = 0; nt < 5; nt++)
#pragma unroll
            for (int e = 0; e < 4; e++) acc[mt][nt][e] = 0.0f;

    const float4* x4 = (const float4*)x + (size_t)blockIdx.x * 128 * 64;
    int f4 = tid & 7;               // float4 slot within 32-k chunk (8 per row)
    int r0 = tid >> 3;              // 16 row-groups

    // ldmatrix address components
    int aRow0 = w * 32 + ((lane >> 3) & 1) * 8 + (lane & 7);  // + mt*16
    int aKoff = (lane >> 4) * 16;                             // + ks*32 bytes
    int l16 = lane & 15;
    int bN = (l16 & 7);                                       // + nt*8
    int bKoff = (l16 >> 3) * 16;                              // + kglob*2 bytes

#pragma unroll 1
    for (int c = 0; c < 8; c++) {
        __syncthreads();            // A smem reuse barrier (also covers B copy at c=0)
        // ---- stage A chunk: 128 rows x 32 k, coalesced LDG -> bf16 hi/lo ----
#pragma unroll
        for (int rr = 0; rr < 8; rr++) {
            int row = rr * 16 + r0;
            float4 v = __ldcg(&x4[(size_t)row * 64 + c * 8 + f4]);
            float h0 = (float)__float2bfloat16(v.x);
            float h1 = (float)__float2bfloat16(v.y);
            float h2 = (float)__float2bfloat16(v.z);
            float h3 = (float)__float2bfloat16(v.w);
            uint32_t hp0, hp1, lp0, lp1;
            asm("cvt.rn.bf16x2.f32 %0, %1, %2;" : "=r"(hp0) : "f"(h1), "f"(h0));
            asm("cvt.rn.bf16x2.f32 %0, %1, %2;" : "=r"(hp1) : "f"(h3), "f"(h2));
            asm("cvt.rn.bf16x2.f32 %0, %1, %2;" : "=r"(lp0) : "f"(v.y - h1), "f"(v.x - h0));
            asm("cvt.rn.bf16x2.f32 %0, %1, %2;" : "=r"(lp1) : "f"(v.w - h3), "f"(v.z - h2));
            uint32_t off = (uint32_t)row * A_STRIDE_B + (uint32_t)f4 * 8;
            *(unsigned long long*)(smem + SM_AH + off) =
                ((unsigned long long)hp1 << 32) | hp0;
            *(unsigned long long*)(smem + SM_AL + off) =
                ((unsigned long long)lp1 << 32) | lp0;
        }
        __syncthreads();
        // ---- compute: 2 k16 steps ----
#pragma unroll
        for (int ks = 0; ks < 2; ks++) {
            uint32_t ah[2][4], al[2][4];
#pragma unroll
            for (int mt = 0; mt < 2; mt++) {
                uint32_t aoff = (uint32_t)(aRow0 + mt * 16) * A_STRIDE_B
                                + (uint32_t)(ks * 32 + aKoff);
                ldm_x4(ah[mt][0], ah[mt][1], ah[mt][2], ah[mt][3],
                       smb + SM_AH + aoff);
                ldm_x4(al[mt][0], al[mt][1], al[mt][2], al[mt][3],
                       smb + SM_AL + aoff);
            }
            int kglob = c * 32 + ks * 16;
#pragma unroll
            for (int nt = 0; nt < 5; nt++) {
                uint32_t boff = (uint32_t)(nt * 8 + bN) * B_STRIDE_B
                                + (uint32_t)(kglob * 2 + bKoff);
                uint32_t bh[2], bl[2];
                ldm_x2(bh[0], bh[1], smb + SM_BH + boff);
                ldm_x2(bl[0], bl[1], smb + SM_BL + boff);
#pragma unroll
                for (int mt = 0; mt < 2; mt++) {
                    mma_bf16(acc[mt][nt], ah[mt], bh);
                    mma_bf16(acc[mt][nt], ah[mt], bl);
                    mma_bf16(acc[mt][nt], al[mt], bh);
                }
            }
        }
    }

    // ---- epilogue: fragments -> smem y stage [128][41] (reuses A region) ----
    __syncthreads();
    float* ystage = (float*)(smem + SM_AH);
#pragma unroll
    for (int mt = 0; mt < 2; mt++) {
        int r = w * 32 + mt * 16 + (lane >> 2);
        int n0 = 2 * (lane & 3);
#pragma unroll
        for (int nt = 0; nt < 5; nt++) {
            int nn = nt * 8 + n0;
            ystage[r * 41 + nn]           = acc[mt][nt][0];
            ystage[r * 41 + nn + 1]       = acc[mt][nt][1];
            ystage[(r + 8) * 41 + nn]     = acc[mt][nt][2];
            ystage[(r + 8) * 41 + nn + 1] = acc[mt][nt][3];
        }
    }
    __syncthreads();

    // per-thread row: b = tid, t = blockIdx.x (proven epilogue code)
    int t = blockIdx.x;
    int b = tid;
    const float* bs = (const float*)(smem + SM_BIAS);
    {
        float o[OSIZE];
        float y[OSIZE];
#pragma unroll
        for (int cch = 0; cch < OSIZE; cch++)
            y[cch] = ystage[tid * 41 + cch] + bs[cch];
#pragma unroll
        for (int cch = 0; cch < 4; cch++) o[cch] = 1.0f + softplus_f(y[cch]);
#pragma unroll
        for (int cch = 4; cch < 8; cch++) o[cch] = 0.1f + softplus_f(y[cch]);
        float* ewb = g_ew + (size_t)t * NTRANS * NBATCH + b;
#pragma unroll
        for (int cch = 8; cch < OSIZE; cch++) {
            float tr = 5.0f * tanhf(y[cch]);
            o[cch] = tr;                                   // logZ fixed by k3
            ewb[(size_t)(cch - 8) * NBATCH] = __expf(tr);  // coalesced STG.32
        }
#pragma unroll
        for (int cch = 0; cch < OSIZE; cch++)
            ystage[tid * 41 + cch] = o[cch];
    }
    __syncthreads();
    // coalesced readout: 1280 float4 = 128 threads x 10
    float* obase = out + (size_t)t * NBATCH * OSIZE;
#pragma unroll
    for (int q = 0; q < 10; q++) {
        int g4 = q * 128 + tid;
        int g = 4 * g4;
        int rl = g / OSIZE;
        int ch = g - rl * OSIZE;
        const float* sp = ystage + rl * 41 + ch;
        ((float4*)obase)[g4] = make_float4(sp[0], sp[1], sp[2], sp[3]);
    }
}

// ---------------- CRF step in exp domain ----------------
// Transposed layout: e[ch] at g_ew[(t*32+ch)*128 + b] -> coalesced LDG.32.
__device__ __forceinline__ void loadE(float e[NTRANS], int t, int b) {
    const float* p = g_ew + (size_t)t * NTRANS * NBATCH + b;
#pragma unroll
    for (int ch = 0; ch < NTRANS; ch++) e[ch] = p[(size_t)ch * NBATCH];
}

__device__ __forceinline__ void stepf(float p[8], const float e[NTRANS]) {
    float np[8];
#pragma unroll
    for (int i = 0; i < 4; i++) {
        float m = 0.0f, s = 0.0f;
#pragma unroll
        for (int j = 0; j < 8; j++) {
            float v = p[j] * e[i * 8 + j];
            if (j == i || j == i + 4) s += v;   // "stay" terms
            else                      m += v;   // "move" terms
        }
        np[i] = m;
        np[i + 4] = s;
    }
#pragma unroll
    for (int i = 0; i < 8; i++) p[i] = np[i];
}

// ---------------- Kernel 2a: per-chunk matrices, normalized ----------------
__global__ void __launch_bounds__(128, 1) k2a_chunk()
{
    int b = threadIdx.x;           // batch
    int c = blockIdx.x;            // chunk
    int t0 = c * CHUNK;

    float M[8][8];                 // M[j] = column j
#pragma unroll
    for (int j = 0; j < 8; j++)
#pragma unroll
        for (int i = 0; i < 8; i++) M[j][i] = (i == j) ? 1.0f : 0.0f;

    float eA[NTRANS], eB[NTRANS];
    loadE(eA, t0, b);
#pragma unroll 1
    for (int s = 0; s < CHUNK; s += 2) {
        loadE(eB, t0 + s + 1, b);
#pragma unroll
        for (int j = 0; j < 8; j++) stepf(M[j], eA);
        loadE(eA, t0 + s + 2, b);   // s=8 reads pad: discarded
#pragma unroll
        for (int j = 0; j < 8; j++) stepf(M[j], eB);
    }

    // normalize by exact power of two (max entry -> [1,2))
    float maxv = 0.0f;
#pragma unroll
    for (int j = 0; j < 8; j++)
#pragma unroll
        for (int i = 0; i < 8; i++) maxv = fmaxf(maxv, M[j][i]);
    int e = (int)(__float_as_uint(maxv) >> 23) - 127;
    float scale = __uint_as_float((unsigned)(127 - e) << 23);
#pragma unroll
    for (int j = 0; j < 8; j++)
#pragma unroll
        for (int i = 0; i < 8; i++) M[j][i] *= scale;
    g_chunkE[c * NBATCH + b] = e;

    float4* dst = (float4*)g_chunkM;
#pragma unroll
    for (int j = 0; j < 8; j++) {
        dst[((size_t)c * 16 + 2 * j)     * NBATCH + b] = make_float4(M[j][0], M[j][1], M[j][2], M[j][3]);
        dst[((size_t)c * 16 + 2 * j + 1) * NBATCH + b] = make_float4(M[j][4], M[j][5], M[j][6], M[j][7]);
    }
}

// load matrix as u64 column-pairs: m[4*j+qq] = (M[j][2qq], M[j][2qq+1])
__device__ __forceinline__ void loadMp(unsigned long long m[32],
                                       const float* srcM, int c, int b) {
    const float4* p4 = (const float4*)srcM;
#pragma unroll
    for (int q = 0; q < 16; q++) {
        float4 t = p4[((size_t)c * 16 + q) * NBATCH + b];   // coalesced
        m[2 * q]     = pack2(t.x, t.y);
        m[2 * q + 1] = pack2(t.z, t.w);
    }
}

// ---------------- Kernel 2b: group products of 20 chunk matrices ------------
// grid 10 x 128. G <- M_{20g+19}...M_{20g}. Normalized-chunk entries <= 2 ->
// product entries <= 8^19 * 2^20 = 2^77 < fp32 max: no renorm needed.
__global__ void __launch_bounds__(128, 1) k2b_grp()
{
    int b = threadIdx.x;
    int g = blockIdx.x;

    float G[8][8];                  // G[j] = column j
    {
        const float4* p4 = (const float4*)g_chunkM;
#pragma unroll
        for (int q = 0; q < 16; q++) {
            float4 t = p4[((size_t)(g * GRP) * 16 + q) * NBATCH + b];
            int j = q >> 1, h = (q & 1) * 4;
            G[j][h] = t.x; G[j][h + 1] = t.y; G[j][h + 2] = t.z; G[j][h + 3] = t.w;
        }
    }

#pragma unroll 1
    for (int s = 1; s < GRP; s++) {
        unsigned long long A[32];
        loadMp(A, g_chunkM, g * GRP + s, b);
#pragma unroll
        for (int j = 0; j < 8; j++) {
            unsigned long long nv[4];
#pragma unroll
            for (int qq = 0; qq < 4; qq++) nv[qq] = pack2(0.0f, 0.0f);
#pragma unroll
            for (int jj = 0; jj < 8; jj++) {
                unsigned long long vj = pack2(G[j][jj], G[j][jj]);
#pragma unroll
                for (int qq = 0; qq < 4; qq++)
                    nv[qq] = fma2(A[4 * jj + qq], vj, nv[qq]);
            }
#pragma unroll
            for (int qq = 0; qq < 4; qq++)
                unpack2(nv[qq], G[j][2 * qq], G[j][2 * qq + 1]);
        }
    }

    int esum = 0;
#pragma unroll
    for (int s = 0; s < GRP; s++) esum += g_chunkE[(g * GRP + s) * NBATCH + b];
    g_grpE[g * NBATCH + b] = esum;

    float4* dst = (float4*)g_grpM;
#pragma unroll
    for (int j = 0; j < 8; j++) {
        dst[((size_t)g * 16 + 2 * j)     * NBATCH + b] = make_float4(G[j][0], G[j][1], G[j][2], G[j][3]);
        dst[((size_t)g * 16 + 2 * j + 1) * NBATCH + b] = make_float4(G[j][4], G[j][5], G[j][6], G[j][7]);
    }
}

// ---------------- Kernel 2c: two independent 5-deep folds -------------------
__device__ __forceinline__ void foldR(const unsigned long long m[32],
                                      float v[8], int& esum) {
    unsigned long long nv[4];
#pragma unroll
    for (int qq = 0; qq < 4; qq++) nv[qq] = pack2(0.0f, 0.0f);
#pragma unroll
    for (int j = 0; j < 8; j++) {
        unsigned long long vj = pack2(v[j], v[j]);
#pragma unroll
        for (int qq = 0; qq < 4; qq++)
            nv[qq] = fma2(m[4 * j + qq], vj, nv[qq]);
    }
    unsigned long long t = add2(add2(nv[0], nv[1]), add2(nv[2], nv[3]));
    float slo, shi;
    unpack2(t, slo, shi);
    float S = slo + shi;
    int e = (int)(__float_as_uint(S) >> 23) - 127;
    float scale = __uint_as_float((unsigned)(127 - e) << 23);   // exact 2^-e
    esum += e;
    unsigned long long s2 = pack2(scale, scale);
#pragma unroll
    for (int qq = 0; qq < 4; qq++) {
        unsigned long long u = mul2(nv[qq], s2);
        unpack2(u, v[2 * qq], v[2 * qq + 1]);
    }
}

__device__ __forceinline__ void foldL(const unsigned long long m[32],
                                      float u[8], int& esum) {
    unsigned long long up[4];
#pragma unroll
    for (int qq = 0; qq < 4; qq++) up[qq] = pack2(u[2 * qq], u[2 * qq + 1]);
    float nu[8];
#pragma unroll
    for (int j = 0; j < 8; j++) {
        unsigned long long d = mul2(m[4 * j], up[0]);
#pragma unroll
        for (int qq = 1; qq < 4; qq++)
            d = fma2(m[4 * j + qq], up[qq], d);
        float lo, hi;
        unpack2(d, lo, hi);
        nu[j] = lo + hi;
    }
    float S = ((nu[0] + nu[1]) + (nu[2] + nu[3])) + ((nu[4] + nu[5]) + (nu[6] + nu[7]));
    int e = (int)(__float_as_uint(S) >> 23) - 127;
    float scale = __uint_as_float((unsigned)(127 - e) << 23);
    esum += e;
#pragma unroll
    for (int j = 0; j < 8; j++) u[j] = nu[j] * scale;
}

__global__ void __launch_bounds__(32, 1) k2c_combine()
{
    int b = blockIdx.x * 32 + threadIdx.x;

    int esum = 0;
#pragma unroll
    for (int g = 0; g < NGRP; g++) esum += g_grpE[g * NBATCH + b];

    float v[8], u[8];
#pragma unroll
    for (int i = 0; i < 8; i++) { v[i] = 1.0f; u[i] = 1.0f; }

#pragma unroll 1
    for (int s = 0; s < NGRP / 2; s++) {
        unsigned long long mV[32], mU[32];
        loadMp(mV, g_grpM, s, b);               // R chain: G_0 .. G_4
        loadMp(mU, g_grpM, NGRP - 1 - s, b);    // L chain: G_9 .. G_5
        foldR(mV, v, esum);
        foldL(mU, u, esum);
    }

    float S = 0.0f;
#pragma unroll
    for (int i = 0; i < 8; i++) S = fmaf(u[i], v[i], S);
    double lz = ((double)esum * 0.69314718055994530942 + log((double)S))
                / (double)NTIME;
    g_logZ[b] = (float)lz;
}

// ---------------- Kernel 3: out[..., 8:40] -= logZ[b] ----------------
__global__ void __launch_bounds__(256) k3_fixup(float* __restrict__ out)
{
    int q = blockIdx.x * 256 + threadIdx.x;      // one float4 of 32 trans channels
    if (q >= NTIME * NBATCH * 8) return;
    int tb = q >> 3;
    int sub = q & 7;
    float lz = g_logZ[tb & (NBATCH - 1)];
    float4* ptr = (float4*)(out + (size_t)tb * OSIZE + 8) + sub;
    float4 v = *ptr;
    v.x -= lz; v.y -= lz; v.z -= lz; v.w -= lz;
    *ptr = v;
}

extern "C" void kernel_launch(void* const* d_in, const int* in_sizes, int n_in,
                              void* d_out, int out_size)
{
    const float* x = (const float*)d_in[0];
    const float* W = (const float*)d_in[1];
    const float* b = (const float*)d_in[2];
    float* out = (float*)d_out;

    static int smem_set = 0;
    if (!smem_set) {
        cudaFuncSetAttribute(k1_gemm_mma,
                             cudaFuncAttributeMaxDynamicSharedMemorySize, K1_SMEM);
        smem_set = 1;
    }

    k0_prepw<<<(OSIZE * 132 + 255) / 256, 256>>>(W);
    k1_gemm_mma<<<NTIME, 128, K1_SMEM>>>(x, W, b, out);
    k2a_chunk<<<NCHUNK, 128>>>();
    k2b_grp<<<NGRP, 128>>>();
    k2c_combine<<<NBATCH / 32, 32>>>();
    k3_fixup<<<(NTIME * NBATCH * 8 + 255) / 256, 256>>>(out);
}